// round 3
// baseline (speedup 1.0000x reference)
#include <cuda_runtime.h>
#include <math.h>

#define N_NODE        1000000
#define N_BOND        100000
#define KTW           40
#define MAX_ORDER     8
#define N_DOMAIN      10000
#define N_GROUP       12500        // N_BOND / MAX_ORDER
#define N_TW          500000       // N_GROUP * KTW (only these nodes twisted)
#define SIGMA_MAXF    3.14159265358979323846f

#define NBLK          98
#define NTHR          128

// Double-buffered per-group affine transform (9 R + 3 t)
__device__ __align__(16) float g_M[2][N_GROUP * 12];
// software grid barrier state (self-resetting: count returns to 0 each barrier)
__device__ int g_count = 0;
__device__ int g_epoch = 0;

__device__ __forceinline__ void grid_bar() {
    __syncthreads();
    if (threadIdx.x == 0) {
        __threadfence();                       // publish g_M writes
        int e = *(volatile int*)&g_epoch;      // read epoch BEFORE arriving
        __threadfence();
        int old = atomicAdd(&g_count, 1);
        if (old == NBLK - 1) {
            g_count = 0;
            __threadfence();
            atomicAdd(&g_epoch, 1);            // release
        } else {
            while (*(volatile int*)&g_epoch == e) { }
        }
        __threadfence();                       // acquire
    }
    __syncthreads();
}

// ---------------------------------------------------------------------------
// Fused torsion kernel: angle precompute + 8 compose passes, grid-barriered.
// Thread g owns group g; M kept in registers, published per pass for gathers.
// ---------------------------------------------------------------------------
__global__ __launch_bounds__(NTHR) void k_fused(const float* __restrict__ pos,
                                                const int*   __restrict__ anno,
                                                const float* __restrict__ info,
                                                const float* __restrict__ eps,
                                                const float* __restrict__ uni,
                                                const int*   __restrict__ fprio) {
    int g = blockIdx.x * NTHR + threadIdx.x;
    bool act = (g < N_GROUP);

    int   U[MAX_ORDER], Vn[MAX_ORDER];
    float S[MAX_ORDER], C[MAX_ORDER];

    if (act) {
        // anno rows 8g..8g+7: 24 contiguous ints, 16B-aligned (96g bytes)
        const int4* a4 = (const int4*)(anno + 24 * g);
        int4 A0 = a4[0], A1 = a4[1], A2 = a4[2], A3 = a4[3], A4 = a4[4], A5 = a4[5];
        int aw[24] = {A0.x,A0.y,A0.z,A0.w, A1.x,A1.y,A1.z,A1.w,
                      A2.x,A2.y,A2.z,A2.w, A3.x,A3.y,A3.z,A3.w,
                      A4.x,A4.y,A4.z,A4.w, A5.x,A5.y,A5.z,A5.w};
        #pragma unroll
        for (int o = 0; o < MAX_ORDER; o++) {
            U[o]  = aw[3 * o + 1];
            Vn[o] = aw[3 * o + 2];
        }
        const float4* i4 = (const float4*)(info + 8 * g);
        const float4* e4 = (const float4*)(eps + 8 * g);
        const float4* u4 = (const float4*)(uni + 8 * g);
        float4 I0 = i4[0], I1 = i4[1];
        float4 E0 = e4[0], E1 = e4[1];
        float4 X0 = u4[0], X1 = u4[1];
        float il[8]  = {I0.x,I0.y,I0.z,I0.w, I1.x,I1.y,I1.z,I1.w};
        float ep[8]  = {E0.x,E0.y,E0.z,E0.w, E1.x,E1.y,E1.z,E1.w};
        float un[8]  = {X0.x,X0.y,X0.z,X0.w, X1.x,X1.y,X1.z,X1.w};
        int fp = fprio[0];
        #pragma unroll
        for (int o = 0; o < MAX_ORDER; o++) {
            float ang = ep[o] * (1.0f - il[o]) * SIGMA_MAXF;
            if (fp != 0 && il[o] == 0.0f) ang = un[o];
            double ds, dc;
            sincos((double)ang, &ds, &dc);   // full precision independent of fast-math
            S[o] = (float)ds;
            C[o] = (float)dc;
        }
    }

    float M[12];  // own composed affine (regs)

    #pragma unroll 1
    for (int o = 0; o < MAX_ORDER; o++) {
        if (o) grid_bar();
        if (act) {
            int cur = o & 1;          // valid buffer for reads (o>0)
            // endpoint positions under current transform
            float pux, puy, puz, pvx, pvy, pvz;
            {
                int n = U[o];
                float x = pos[3*n], y = pos[3*n+1], z = pos[3*n+2];
                if (o > 0 && n < N_TW) {
                    const float4* m4 = (const float4*)&g_M[cur][(n / KTW) * 12];
                    float4 m0 = m4[0], m1 = m4[1], m2 = m4[2];
                    pux = m0.x*x + m0.y*y + m0.z*z + m2.y;
                    puy = m0.w*x + m1.x*y + m1.y*z + m2.z;
                    puz = m1.z*x + m1.w*y + m2.x*z + m2.w;
                } else { pux = x; puy = y; puz = z; }
            }
            {
                int n = Vn[o];
                float x = pos[3*n], y = pos[3*n+1], z = pos[3*n+2];
                if (o > 0 && n < N_TW) {
                    const float4* m4 = (const float4*)&g_M[cur][(n / KTW) * 12];
                    float4 m0 = m4[0], m1 = m4[1], m2 = m4[2];
                    pvx = m0.x*x + m0.y*y + m0.z*z + m2.y;
                    pvy = m0.w*x + m1.x*y + m1.y*z + m2.z;
                    pvz = m1.z*x + m1.w*y + m2.x*z + m2.w;
                } else { pvx = x; pvy = y; pvz = z; }
            }

            float ax = pvx - pux, ay = pvy - puy, az = pvz - puz;
            float nrm = sqrtf(ax*ax + ay*ay + az*az) + 1e-12f;
            float inv = 1.0f / nrm;
            ax *= inv; ay *= inv; az *= inv;

            float s = S[o], c = C[o], omc = 1.0f - c;
            float r0 = c + omc*ax*ax;
            float r1 = -s*az + omc*ax*ay;
            float r2 =  s*ay + omc*ax*az;
            float r3 =  s*az + omc*ay*ax;
            float r4 = c + omc*ay*ay;
            float r5 = -s*ax + omc*ay*az;
            float r6 = -s*ay + omc*az*ax;
            float r7 =  s*ax + omc*az*ay;
            float r8 = c + omc*az*az;
            float t0 = pvx - (r0*pvx + r1*pvy + r2*pvz);
            float t1 = pvy - (r3*pvx + r4*pvy + r5*pvz);
            float t2 = pvz - (r6*pvx + r7*pvy + r8*pvz);

            if (o == 0) {
                M[0]=r0; M[1]=r1; M[2]=r2; M[3]=r3; M[4]=r4; M[5]=r5;
                M[6]=r6; M[7]=r7; M[8]=r8; M[9]=t0; M[10]=t1; M[11]=t2;
            } else {
                float m0=M[0],m1=M[1],m2=M[2],m3=M[3],m4=M[4],m5=M[5];
                float m6=M[6],m7=M[7],m8=M[8],mt0=M[9],mt1=M[10],mt2=M[11];
                M[0] = r0*m0 + r1*m3 + r2*m6;
                M[1] = r0*m1 + r1*m4 + r2*m7;
                M[2] = r0*m2 + r1*m5 + r2*m8;
                M[3] = r3*m0 + r4*m3 + r5*m6;
                M[4] = r3*m1 + r4*m4 + r5*m7;
                M[5] = r3*m2 + r4*m5 + r5*m8;
                M[6] = r6*m0 + r7*m3 + r8*m6;
                M[7] = r6*m1 + r7*m4 + r8*m7;
                M[8] = r6*m2 + r7*m5 + r8*m8;
                M[9]  = r0*mt0 + r1*mt1 + r2*mt2 + t0;
                M[10] = r3*mt0 + r4*mt1 + r5*mt2 + t1;
                M[11] = r6*mt0 + r7*mt1 + r8*mt2 + t2;
            }
            // publish for other groups' gathers next pass (and final for kabsch)
            float4* w4 = (float4*)&g_M[(o + 1) & 1][g * 12];
            w4[0] = make_float4(M[0], M[1], M[2], M[3]);
            w4[1] = make_float4(M[4], M[5], M[6], M[7]);
            w4[2] = make_float4(M[8], M[9], M[10], M[11]);
        }
    }
    // final M lives in g_M[0] (pass 7 wrote buffer (7+1)&1 = 0)
}

// ---------------------------------------------------------------------------
// Kabsch: one warp per domain (100 contiguous nodes); P = M_g * pos on the fly.
// Horn quaternion (== SVD Kabsch with proper-rotation sign fix).
// ---------------------------------------------------------------------------
__global__ __launch_bounds__(256) void k_kabsch(const float* __restrict__ pos,
                                                float* __restrict__ out) {
    int wid  = (blockIdx.x * blockDim.x + threadIdx.x) >> 5;
    int lane = threadIdx.x & 31;
    if (wid >= N_DOMAIN) return;
    int base = wid * 100;
    const float* __restrict__ M = g_M[0];

    float P[4][3];
    float sp0=0,sp1=0,sp2=0,sq0=0,sq1=0,sq2=0;
    float h00=0,h01=0,h02=0,h10=0,h11=0,h12=0,h20=0,h21=0,h22=0;

    #pragma unroll
    for (int i = 0; i < 4; i++) {
        int idx = lane + 32 * i;
        P[i][0] = P[i][1] = P[i][2] = 0.0f;
        if (idx < 100) {
            int n = base + idx;
            float qx = pos[3*n], qy = pos[3*n+1], qz = pos[3*n+2];
            float px, py, pz;
            if (n < N_TW) {
                const float4* m4 = (const float4*)&M[(n / KTW) * 12];
                float4 m0 = m4[0], m1 = m4[1], m2 = m4[2];
                px = m0.x*qx + m0.y*qy + m0.z*qz + m2.y;
                py = m0.w*qx + m1.x*qy + m1.y*qz + m2.z;
                pz = m1.z*qx + m1.w*qy + m2.x*qz + m2.w;
            } else { px = qx; py = qy; pz = qz; }
            P[i][0]=px; P[i][1]=py; P[i][2]=pz;
            sp0+=px; sp1+=py; sp2+=pz;
            sq0+=qx; sq1+=qy; sq2+=qz;
            h00+=px*qx; h01+=px*qy; h02+=px*qz;
            h10+=py*qx; h11+=py*qy; h12+=py*qz;
            h20+=pz*qx; h21+=pz*qy; h22+=pz*qz;
        }
    }

    #define WRED(v) { v += __shfl_xor_sync(0xffffffffu, v, 16); \
                      v += __shfl_xor_sync(0xffffffffu, v, 8);  \
                      v += __shfl_xor_sync(0xffffffffu, v, 4);  \
                      v += __shfl_xor_sync(0xffffffffu, v, 2);  \
                      v += __shfl_xor_sync(0xffffffffu, v, 1); }
    WRED(sp0) WRED(sp1) WRED(sp2) WRED(sq0) WRED(sq1) WRED(sq2)
    WRED(h00) WRED(h01) WRED(h02) WRED(h10) WRED(h11) WRED(h12)
    WRED(h20) WRED(h21) WRED(h22)
    #undef WRED

    const float invc = 0.01f;
    float cpx=sp0*invc, cpy=sp1*invc, cpz=sp2*invc;
    float cqx=sq0*invc, cqy=sq1*invc, cqz=sq2*invc;
    float H00=h00-sp0*sq0*invc, H01=h01-sp0*sq1*invc, H02=h02-sp0*sq2*invc;
    float H10=h10-sp1*sq0*invc, H11=h11-sp1*sq1*invc, H12=h12-sp1*sq2*invc;
    float H20=h20-sp2*sq0*invc, H21=h21-sp2*sq1*invc, H22=h22-sp2*sq2*invc;

    float A[4][4];
    A[0][0] = H00 + H11 + H22;
    A[0][1] = H12 - H21;
    A[0][2] = H20 - H02;
    A[0][3] = H01 - H10;
    A[1][1] = H00 - H11 - H22;
    A[1][2] = H01 + H10;
    A[1][3] = H20 + H02;
    A[2][2] = -H00 + H11 - H22;
    A[2][3] = H12 + H21;
    A[3][3] = -H00 - H11 + H22;
    A[1][0]=A[0][1]; A[2][0]=A[0][2]; A[3][0]=A[0][3];
    A[2][1]=A[1][2]; A[3][1]=A[1][3]; A[3][2]=A[2][3];

    float V[4][4] = {{1,0,0,0},{0,1,0,0},{0,0,1,0},{0,0,0,1}};

    #pragma unroll
    for (int sweep = 0; sweep < 8; sweep++) {
        #pragma unroll
        for (int p = 0; p < 3; p++) {
            #pragma unroll
            for (int q = p + 1; q < 4; q++) {
                float apq = A[p][q];
                if (fabsf(apq) > 1e-30f) {
                    float theta = (A[q][q] - A[p][p]) / (2.0f * apq);
                    float tt = 1.0f / (fabsf(theta) + sqrtf(theta*theta + 1.0f));
                    if (theta < 0.0f) tt = -tt;
                    float cc = rsqrtf(tt*tt + 1.0f);
                    float ss = tt * cc;
                    #pragma unroll
                    for (int k = 0; k < 4; k++) {
                        float t1 = A[p][k], t2 = A[q][k];
                        A[p][k] = cc*t1 - ss*t2;
                        A[q][k] = ss*t1 + cc*t2;
                    }
                    #pragma unroll
                    for (int k = 0; k < 4; k++) {
                        float t1 = A[k][p], t2 = A[k][q];
                        A[k][p] = cc*t1 - ss*t2;
                        A[k][q] = ss*t1 + cc*t2;
                    }
                    #pragma unroll
                    for (int k = 0; k < 4; k++) {
                        float t1 = V[k][p], t2 = V[k][q];
                        V[k][p] = cc*t1 - ss*t2;
                        V[k][q] = ss*t1 + cc*t2;
                    }
                }
            }
        }
    }

    int kbest = 0;
    float best = A[0][0];
    #pragma unroll
    for (int k = 1; k < 4; k++)
        if (A[k][k] > best) { best = A[k][k]; kbest = k; }
    float qw=V[0][kbest], qx=V[1][kbest], qy=V[2][kbest], qz=V[3][kbest];
    float qn = rsqrtf(qw*qw + qx*qx + qy*qy + qz*qz);
    qw*=qn; qx*=qn; qy*=qn; qz*=qn;

    float R00 = qw*qw + qx*qx - qy*qy - qz*qz;
    float R01 = 2.0f*(qx*qy - qw*qz);
    float R02 = 2.0f*(qx*qz + qw*qy);
    float R10 = 2.0f*(qx*qy + qw*qz);
    float R11 = qw*qw - qx*qx + qy*qy - qz*qz;
    float R12 = 2.0f*(qy*qz - qw*qx);
    float R20 = 2.0f*(qx*qz - qw*qy);
    float R21 = 2.0f*(qy*qz + qw*qx);
    float R22 = qw*qw - qx*qx - qy*qy + qz*qz;

    float tx = cqx - (R00*cpx + R01*cpy + R02*cpz);
    float ty = cqy - (R10*cpx + R11*cpy + R12*cpz);
    float tz = cqz - (R20*cpx + R21*cpy + R22*cpz);

    #pragma unroll
    for (int i = 0; i < 4; i++) {
        int idx = lane + 32 * i;
        if (idx < 100) {
            int n = base + idx;
            float px=P[i][0], py=P[i][1], pz=P[i][2];
            out[3*n+0] = R00*px + R01*py + R02*pz + tx;
            out[3*n+1] = R10*px + R11*py + R12*pz + ty;
            out[3*n+2] = R20*px + R21*py + R22*pz + tz;
        }
    }
}

// ---------------------------------------------------------------------------
extern "C" void kernel_launch(void* const* d_in, const int* in_sizes, int n_in,
                              void* d_out, int out_size) {
    const float* pos   = (const float*)d_in[0];
    const float* info  = (const float*)d_in[1];
    const int*   anno  = (const int*)d_in[2];
    const float* eps   = (const float*)d_in[6];
    const float* uni   = (const float*)d_in[7];
    const int*   fprio = (const int*)d_in[8];
    float* out = (float*)d_out;

    k_fused<<<NBLK, NTHR>>>(pos, anno, info, eps, uni, fprio);
    k_kabsch<<<(N_DOMAIN * 32 + 255) / 256, 256>>>(pos, out);
}

// round 4
// speedup vs baseline: 1.5726x; 1.5726x over previous
#include <cuda_runtime.h>
#include <math.h>

#define N_NODE        1000000
#define N_BOND        100000
#define KTW           40
#define MAX_ORDER     8
#define N_DOMAIN      10000
#define N_GROUP       12500        // N_BOND / MAX_ORDER
#define N_TW          500000       // N_GROUP * KTW (only these nodes twisted)
#define SIGMA_MAXF    3.14159265358979323846f

#define NBLK          98
#define NTHR          128

// Scratch
__device__ __align__(16) float g_M[2][N_GROUP * 12];   // per-group affine (dbl-buffered)
__device__ __align__(16) float g_red[N_DOMAIN * 16];   // per-domain H(9)+sp(3)+sq(3)+pad
__device__ __align__(16) float g_RT[N_DOMAIN * 12];    // per-domain R(9)+t(3)
__device__ int g_count = 0;
__device__ int g_epoch = 0;

__device__ __forceinline__ void grid_bar() {
    __syncthreads();
    if (threadIdx.x == 0) {
        __threadfence();
        int e = *(volatile int*)&g_epoch;
        __threadfence();
        int old = atomicAdd(&g_count, 1);
        if (old == NBLK - 1) {
            g_count = 0;
            __threadfence();
            atomicAdd(&g_epoch, 1);
        } else {
            while (*(volatile int*)&g_epoch == e) { __nanosleep(40); }
        }
        __threadfence();
    }
    __syncthreads();
}

// ---------------------------------------------------------------------------
// Fused torsion: angle precompute + 8 compose passes with grid barrier.
// Thread g owns group g; composed affine M stays in registers.
// ---------------------------------------------------------------------------
__global__ __launch_bounds__(NTHR) void k_fused(const float* __restrict__ pos,
                                                const int*   __restrict__ anno,
                                                const float* __restrict__ info,
                                                const float* __restrict__ eps,
                                                const float* __restrict__ uni,
                                                const int*   __restrict__ fprio) {
    int g = blockIdx.x * NTHR + threadIdx.x;
    bool act = (g < N_GROUP);

    int   U[MAX_ORDER], Vn[MAX_ORDER];
    float S[MAX_ORDER], C[MAX_ORDER];

    if (act) {
        const int4* a4 = (const int4*)(anno + 24 * g);
        int4 A0 = a4[0], A1 = a4[1], A2 = a4[2], A3 = a4[3], A4 = a4[4], A5 = a4[5];
        int aw[24] = {A0.x,A0.y,A0.z,A0.w, A1.x,A1.y,A1.z,A1.w,
                      A2.x,A2.y,A2.z,A2.w, A3.x,A3.y,A3.z,A3.w,
                      A4.x,A4.y,A4.z,A4.w, A5.x,A5.y,A5.z,A5.w};
        #pragma unroll
        for (int o = 0; o < MAX_ORDER; o++) {
            U[o]  = aw[3 * o + 1];
            Vn[o] = aw[3 * o + 2];
        }
        const float4* i4 = (const float4*)(info + 8 * g);
        const float4* e4 = (const float4*)(eps + 8 * g);
        const float4* u4 = (const float4*)(uni + 8 * g);
        float4 I0 = i4[0], I1 = i4[1];
        float4 E0 = e4[0], E1 = e4[1];
        float4 X0 = u4[0], X1 = u4[1];
        float il[8] = {I0.x,I0.y,I0.z,I0.w, I1.x,I1.y,I1.z,I1.w};
        float ep[8] = {E0.x,E0.y,E0.z,E0.w, E1.x,E1.y,E1.z,E1.w};
        float un[8] = {X0.x,X0.y,X0.z,X0.w, X1.x,X1.y,X1.z,X1.w};
        int fp = fprio[0];
        #pragma unroll
        for (int o = 0; o < MAX_ORDER; o++) {
            float ang = ep[o] * (1.0f - il[o]) * SIGMA_MAXF;
            if (fp != 0 && il[o] == 0.0f) ang = un[o];
            double ds, dc;
            sincos((double)ang, &ds, &dc);
            S[o] = (float)ds;
            C[o] = (float)dc;
        }
    }

    float M[12];

    #pragma unroll 1
    for (int o = 0; o < MAX_ORDER; o++) {
        if (o) grid_bar();
        if (act) {
            int cur = o & 1;
            float pux, puy, puz, pvx, pvy, pvz;
            {
                int n = U[o];
                float x = pos[3*n], y = pos[3*n+1], z = pos[3*n+2];
                if (o > 0 && n < N_TW) {
                    const float4* m4 = (const float4*)&g_M[cur][(n / KTW) * 12];
                    float4 m0 = m4[0], m1 = m4[1], m2 = m4[2];
                    pux = m0.x*x + m0.y*y + m0.z*z + m2.y;
                    puy = m0.w*x + m1.x*y + m1.y*z + m2.z;
                    puz = m1.z*x + m1.w*y + m2.x*z + m2.w;
                } else { pux = x; puy = y; puz = z; }
            }
            {
                int n = Vn[o];
                float x = pos[3*n], y = pos[3*n+1], z = pos[3*n+2];
                if (o > 0 && n < N_TW) {
                    const float4* m4 = (const float4*)&g_M[cur][(n / KTW) * 12];
                    float4 m0 = m4[0], m1 = m4[1], m2 = m4[2];
                    pvx = m0.x*x + m0.y*y + m0.z*z + m2.y;
                    pvy = m0.w*x + m1.x*y + m1.y*z + m2.z;
                    pvz = m1.z*x + m1.w*y + m2.x*z + m2.w;
                } else { pvx = x; pvy = y; pvz = z; }
            }

            float ax = pvx - pux, ay = pvy - puy, az = pvz - puz;
            float nrm = sqrtf(ax*ax + ay*ay + az*az) + 1e-12f;
            float inv = 1.0f / nrm;
            ax *= inv; ay *= inv; az *= inv;

            float s = S[o], c = C[o], omc = 1.0f - c;
            float r0 = c + omc*ax*ax;
            float r1 = -s*az + omc*ax*ay;
            float r2 =  s*ay + omc*ax*az;
            float r3 =  s*az + omc*ay*ax;
            float r4 = c + omc*ay*ay;
            float r5 = -s*ax + omc*ay*az;
            float r6 = -s*ay + omc*az*ax;
            float r7 =  s*ax + omc*az*ay;
            float r8 = c + omc*az*az;
            float t0 = pvx - (r0*pvx + r1*pvy + r2*pvz);
            float t1 = pvy - (r3*pvx + r4*pvy + r5*pvz);
            float t2 = pvz - (r6*pvx + r7*pvy + r8*pvz);

            if (o == 0) {
                M[0]=r0; M[1]=r1; M[2]=r2; M[3]=r3; M[4]=r4; M[5]=r5;
                M[6]=r6; M[7]=r7; M[8]=r8; M[9]=t0; M[10]=t1; M[11]=t2;
            } else {
                float m0=M[0],m1=M[1],m2=M[2],m3=M[3],m4=M[4],m5=M[5];
                float m6=M[6],m7=M[7],m8=M[8],mt0=M[9],mt1=M[10],mt2=M[11];
                M[0] = r0*m0 + r1*m3 + r2*m6;
                M[1] = r0*m1 + r1*m4 + r2*m7;
                M[2] = r0*m2 + r1*m5 + r2*m8;
                M[3] = r3*m0 + r4*m3 + r5*m6;
                M[4] = r3*m1 + r4*m4 + r5*m7;
                M[5] = r3*m2 + r4*m5 + r5*m8;
                M[6] = r6*m0 + r7*m3 + r8*m6;
                M[7] = r6*m1 + r7*m4 + r8*m7;
                M[8] = r6*m2 + r7*m5 + r8*m8;
                M[9]  = r0*mt0 + r1*mt1 + r2*mt2 + t0;
                M[10] = r3*mt0 + r4*mt1 + r5*mt2 + t1;
                M[11] = r6*mt0 + r7*mt1 + r8*mt2 + t2;
            }
            float4* w4 = (float4*)&g_M[(o + 1) & 1][g * 12];
            w4[0] = make_float4(M[0], M[1], M[2], M[3]);
            w4[1] = make_float4(M[4], M[5], M[6], M[7]);
            w4[2] = make_float4(M[8], M[9], M[10], M[11]);
        }
    }
    // final M in g_M[0]
}

// helper: P = M_g * q (or q when untwisted)
__device__ __forceinline__ float3 tw_pos(const float* __restrict__ Mbuf, int n,
                                         float qx, float qy, float qz) {
    if (n < N_TW) {
        const float4* m4 = (const float4*)&Mbuf[(n / KTW) * 12];
        float4 m0 = m4[0], m1 = m4[1], m2 = m4[2];
        return make_float3(m0.x*qx + m0.y*qy + m0.z*qz + m2.y,
                           m0.w*qx + m1.x*qy + m1.y*qz + m2.z,
                           m1.z*qx + m1.w*qy + m2.x*qz + m2.w);
    }
    return make_float3(qx, qy, qz);
}

// ---------------------------------------------------------------------------
// Stage 1: per-domain reductions (warp per domain). Writes H(9)+sp(3)+sq(3).
// ---------------------------------------------------------------------------
__global__ __launch_bounds__(256) void k_reduce(const float* __restrict__ pos) {
    int wid  = (blockIdx.x * blockDim.x + threadIdx.x) >> 5;
    int lane = threadIdx.x & 31;
    if (wid >= N_DOMAIN) return;
    int base = wid * 100;
    const float* __restrict__ M = g_M[0];

    float sp0=0,sp1=0,sp2=0,sq0=0,sq1=0,sq2=0;
    float h00=0,h01=0,h02=0,h10=0,h11=0,h12=0,h20=0,h21=0,h22=0;

    #pragma unroll
    for (int i = 0; i < 4; i++) {
        int idx = lane + 32 * i;
        if (idx < 100) {
            int n = base + idx;
            float qx = pos[3*n], qy = pos[3*n+1], qz = pos[3*n+2];
            float3 P = tw_pos(M, n, qx, qy, qz);
            float px = P.x, py = P.y, pz = P.z;
            sp0+=px; sp1+=py; sp2+=pz;
            sq0+=qx; sq1+=qy; sq2+=qz;
            h00+=px*qx; h01+=px*qy; h02+=px*qz;
            h10+=py*qx; h11+=py*qy; h12+=py*qz;
            h20+=pz*qx; h21+=pz*qy; h22+=pz*qz;
        }
    }

    #define WRED(v) { v += __shfl_xor_sync(0xffffffffu, v, 16); \
                      v += __shfl_xor_sync(0xffffffffu, v, 8);  \
                      v += __shfl_xor_sync(0xffffffffu, v, 4);  \
                      v += __shfl_xor_sync(0xffffffffu, v, 2);  \
                      v += __shfl_xor_sync(0xffffffffu, v, 1); }
    WRED(sp0) WRED(sp1) WRED(sp2) WRED(sq0) WRED(sq1) WRED(sq2)
    WRED(h00) WRED(h01) WRED(h02) WRED(h10) WRED(h11) WRED(h12)
    WRED(h20) WRED(h21) WRED(h22)
    #undef WRED

    if (lane == 0) {
        float4* r = (float4*)&g_red[wid * 16];
        r[0] = make_float4(h00, h01, h02, h10);
        r[1] = make_float4(h11, h12, h20, h21);
        r[2] = make_float4(h22, sp0, sp1, sp2);
        r[3] = make_float4(sq0, sq1, sq2, 0.0f);
    }
}

// ---------------------------------------------------------------------------
// Stage 2: one THREAD per domain — Horn quaternion solve (Jacobi, 6 sweeps).
// ---------------------------------------------------------------------------
__global__ __launch_bounds__(128) void k_solve() {
    int d = blockIdx.x * blockDim.x + threadIdx.x;
    if (d >= N_DOMAIN) return;
    const float4* r = (const float4*)&g_red[d * 16];
    float4 r0 = r[0], r1 = r[1], r2 = r[2], r3 = r[3];
    float h00=r0.x,h01=r0.y,h02=r0.z,h10=r0.w;
    float h11=r1.x,h12=r1.y,h20=r1.z,h21=r1.w;
    float h22=r2.x,sp0=r2.y,sp1=r2.z,sp2=r2.w;
    float sq0=r3.x,sq1=r3.y,sq2=r3.z;

    const float invc = 0.01f;
    float cpx=sp0*invc, cpy=sp1*invc, cpz=sp2*invc;
    float cqx=sq0*invc, cqy=sq1*invc, cqz=sq2*invc;
    float H00=h00-sp0*sq0*invc, H01=h01-sp0*sq1*invc, H02=h02-sp0*sq2*invc;
    float H10=h10-sp1*sq0*invc, H11=h11-sp1*sq1*invc, H12=h12-sp1*sq2*invc;
    float H20=h20-sp2*sq0*invc, H21=h21-sp2*sq1*invc, H22=h22-sp2*sq2*invc;

    float A[4][4];
    A[0][0] = H00 + H11 + H22;
    A[0][1] = H12 - H21;
    A[0][2] = H20 - H02;
    A[0][3] = H01 - H10;
    A[1][1] = H00 - H11 - H22;
    A[1][2] = H01 + H10;
    A[1][3] = H20 + H02;
    A[2][2] = -H00 + H11 - H22;
    A[2][3] = H12 + H21;
    A[3][3] = -H00 - H11 + H22;
    A[1][0]=A[0][1]; A[2][0]=A[0][2]; A[3][0]=A[0][3];
    A[2][1]=A[1][2]; A[3][1]=A[1][3]; A[3][2]=A[2][3];

    float V[4][4] = {{1,0,0,0},{0,1,0,0},{0,0,1,0},{0,0,0,1}};

    #pragma unroll
    for (int sweep = 0; sweep < 6; sweep++) {
        #pragma unroll
        for (int p = 0; p < 3; p++) {
            #pragma unroll
            for (int q = p + 1; q < 4; q++) {
                float apq = A[p][q];
                if (fabsf(apq) > 1e-30f) {
                    float theta = (A[q][q] - A[p][p]) / (2.0f * apq);
                    float tt = 1.0f / (fabsf(theta) + sqrtf(theta*theta + 1.0f));
                    if (theta < 0.0f) tt = -tt;
                    float cc = rsqrtf(tt*tt + 1.0f);
                    float ss = tt * cc;
                    #pragma unroll
                    for (int k = 0; k < 4; k++) {
                        float t1 = A[p][k], t2 = A[q][k];
                        A[p][k] = cc*t1 - ss*t2;
                        A[q][k] = ss*t1 + cc*t2;
                    }
                    #pragma unroll
                    for (int k = 0; k < 4; k++) {
                        float t1 = A[k][p], t2 = A[k][q];
                        A[k][p] = cc*t1 - ss*t2;
                        A[k][q] = ss*t1 + cc*t2;
                    }
                    #pragma unroll
                    for (int k = 0; k < 4; k++) {
                        float t1 = V[k][p], t2 = V[k][q];
                        V[k][p] = cc*t1 - ss*t2;
                        V[k][q] = ss*t1 + cc*t2;
                    }
                }
            }
        }
    }

    int kbest = 0;
    float best = A[0][0];
    #pragma unroll
    for (int k = 1; k < 4; k++)
        if (A[k][k] > best) { best = A[k][k]; kbest = k; }
    float qw=V[0][kbest], qx=V[1][kbest], qy=V[2][kbest], qz=V[3][kbest];
    float qn = rsqrtf(qw*qw + qx*qx + qy*qy + qz*qz);
    qw*=qn; qx*=qn; qy*=qn; qz*=qn;

    float R00 = qw*qw + qx*qx - qy*qy - qz*qz;
    float R01 = 2.0f*(qx*qy - qw*qz);
    float R02 = 2.0f*(qx*qz + qw*qy);
    float R10 = 2.0f*(qx*qy + qw*qz);
    float R11 = qw*qw - qx*qx + qy*qy - qz*qz;
    float R12 = 2.0f*(qy*qz - qw*qx);
    float R20 = 2.0f*(qx*qz - qw*qy);
    float R21 = 2.0f*(qy*qz + qw*qx);
    float R22 = qw*qw - qx*qx - qy*qy + qz*qz;

    float tx = cqx - (R00*cpx + R01*cpy + R02*cpz);
    float ty = cqy - (R10*cpx + R11*cpy + R12*cpz);
    float tz = cqz - (R20*cpx + R21*cpy + R22*cpz);

    float4* w = (float4*)&g_RT[d * 12];
    w[0] = make_float4(R00, R01, R02, R10);
    w[1] = make_float4(R11, R12, R20, R21);
    w[2] = make_float4(R22, tx, ty, tz);
}

// ---------------------------------------------------------------------------
// Stage 3: one thread per node — out = R_d * (M_g * pos) + t_d. Streaming.
// ---------------------------------------------------------------------------
__global__ __launch_bounds__(256) void k_apply(const float* __restrict__ pos,
                                               float* __restrict__ out) {
    int n = blockIdx.x * blockDim.x + threadIdx.x;
    if (n >= N_NODE) return;
    float qx = pos[3*n], qy = pos[3*n+1], qz = pos[3*n+2];
    float3 P = tw_pos(g_M[0], n, qx, qy, qz);

    const float4* r = (const float4*)&g_RT[(n / 100) * 12];
    float4 R0 = r[0], R1 = r[1], R2 = r[2];
    out[3*n+0] = R0.x*P.x + R0.y*P.y + R0.z*P.z + R2.y;
    out[3*n+1] = R0.w*P.x + R1.x*P.y + R1.y*P.z + R2.z;
    out[3*n+2] = R1.z*P.x + R1.w*P.y + R2.x*P.z + R2.w;
}

// ---------------------------------------------------------------------------
extern "C" void kernel_launch(void* const* d_in, const int* in_sizes, int n_in,
                              void* d_out, int out_size) {
    const float* pos   = (const float*)d_in[0];
    const float* info  = (const float*)d_in[1];
    const int*   anno  = (const int*)d_in[2];
    const float* eps   = (const float*)d_in[6];
    const float* uni   = (const float*)d_in[7];
    const int*   fprio = (const int*)d_in[8];
    float* out = (float*)d_out;

    k_fused<<<NBLK, NTHR>>>(pos, anno, info, eps, uni, fprio);
    k_reduce<<<(N_DOMAIN * 32 + 255) / 256, 256>>>(pos);
    k_solve<<<(N_DOMAIN + 127) / 128, 128>>>();
    k_apply<<<(N_NODE + 255) / 256, 256>>>(pos, out);
}